// round 1
// baseline (speedup 1.0000x reference)
#include <cuda_runtime.h>
#include <math_constants.h>

// Problem constants (fixed shape for this problem instance)
#define BB 8
#define SS 512
#define ROWS (BB * SS)
#define VV 32000
#define EPS_SMOOTH 0.1f
#define REP_W 0.2f
#define IGNORE_IDX (-100)

// Scratch (no allocation allowed -> __device__ globals)
__device__ float g_per_tok[ROWS];
__device__ float g_valid[ROWS];
__device__ int   g_pred[ROWS];
__device__ float g_per_b[BB];
__device__ int   g_is64;

// ---------------------------------------------------------------------------
// Kernel 0: detect whether labels buffer is int64 or int32.
// Reads only ROWS 32-bit words (safe under both encodings). If the data is
// little-endian int64, word[2i+1] must equal the sign-extension of word[2i].
// With random labels in [0, 32000) an int32 buffer fails this immediately.
// ---------------------------------------------------------------------------
__global__ void __launch_bounds__(256) detect_label_width(const int* __restrict__ w, int n_words) {
    int tid = threadIdx.x;
    bool ok = true;
    for (int i = tid; i < n_words / 2; i += 256) {
        int lo = w[2 * i];
        int hi = w[2 * i + 1];
        if (hi != (lo < 0 ? -1 : 0)) ok = false;
    }
    unsigned ball = __ballot_sync(0xffffffffu, ok);
    __shared__ unsigned sh[8];
    int wid = tid >> 5;
    if ((tid & 31) == 0) sh[wid] = ball;
    __syncthreads();
    if (tid == 0) {
        bool all = true;
        #pragma unroll
        for (int i = 0; i < 8; i++) all = all && (sh[i] == 0xffffffffu);
        g_is64 = all ? 1 : 0;
    }
}

// ---------------------------------------------------------------------------
// Kernel 1: one block per row. Single pass over V=32000 floats computing:
//   - online logsumexp (running max m, rescaled sum s)
//   - argmax (for rep loss)
//   - sum of logits (for the label-smoothing mean term)
// Then per_tok = lse - (1-eps)*x[label] - eps*mean(x), masked by validity.
// ---------------------------------------------------------------------------
__global__ void __launch_bounds__(256) row_kernel(const float* __restrict__ logits,
                                                  const void* __restrict__ labels) {
    const int row = blockIdx.x;
    const float* __restrict__ x = logits + (size_t)row * VV;
    const int tid = threadIdx.x;

    float m = -CUDART_INF_F;
    float s = 0.f;
    float t = 0.f;
    int   am = 0;

    const float4* __restrict__ x4 = (const float4*)x;
    #define PROC(val, idx)                                    \
        do {                                                  \
            float _v = (val);                                 \
            t += _v;                                          \
            if (_v > m) {                                     \
                s = s * __expf(m - _v) + 1.0f;                \
                m = _v;                                       \
                am = (idx);                                   \
            } else {                                          \
                s += __expf(_v - m);                          \
            }                                                 \
        } while (0)

    for (int i = tid; i < VV / 4; i += 256) {
        float4 v = x4[i];
        int base = i * 4;
        PROC(v.x, base);
        PROC(v.y, base + 1);
        PROC(v.z, base + 2);
        PROC(v.w, base + 3);
    }
    #undef PROC

    // warp reduce (m,s,am,t)
    #pragma unroll
    for (int off = 16; off; off >>= 1) {
        float m2 = __shfl_down_sync(0xffffffffu, m, off);
        float s2 = __shfl_down_sync(0xffffffffu, s, off);
        float t2 = __shfl_down_sync(0xffffffffu, t, off);
        int  am2 = __shfl_down_sync(0xffffffffu, am, off);
        t += t2;
        if (m2 > m || (m2 == m && am2 < am)) am = am2;
        float M = fmaxf(m, m2);
        s = s * __expf(m - M) + s2 * __expf(m2 - M);
        m = M;
    }

    __shared__ float shm[8], shs[8], sht[8];
    __shared__ int   sha[8];
    int wid = tid >> 5;
    if ((tid & 31) == 0) { shm[wid] = m; shs[wid] = s; sht[wid] = t; sha[wid] = am; }
    __syncthreads();

    if (tid == 0) {
        m = shm[0]; s = shs[0]; t = sht[0]; am = sha[0];
        #pragma unroll
        for (int i = 1; i < 8; i++) {
            float m2 = shm[i], s2 = shs[i], t2 = sht[i];
            int am2 = sha[i];
            t += t2;
            if (m2 > m || (m2 == m && am2 < am)) am = am2;
            float M = fmaxf(m, m2);
            s = s * __expf(m - M) + s2 * __expf(m2 - M);
            m = M;
        }
        float lse = m + __logf(s);

        long long lab;
        if (g_is64) lab = ((const long long*)labels)[row];
        else        lab = (long long)(((const int*)labels)[row]);
        bool valid = (lab != IGNORE_IDX);
        int  li = valid ? (int)lab : 0;
        float xl = __ldg(&x[li]);

        float per = lse - (1.0f - EPS_SMOOTH) * xl - EPS_SMOOTH * (t / (float)VV);
        g_per_tok[row] = valid ? per : 0.f;
        g_valid[row]   = valid ? 1.f : 0.f;
        g_pred[row]    = am;
    }
}

// ---------------------------------------------------------------------------
// Kernel 2: rep loss, one block per batch row. O(S^2) shared-memory compares
// replicate the unique/counts/entropy semantics exactly (first-occurrence
// trick: each unique value contributes once to entropy and n_unique).
// ---------------------------------------------------------------------------
__global__ void __launch_bounds__(512) rep_kernel() {
    const int b = blockIdx.x;
    const int i = threadIdx.x;

    __shared__ int   sp[SS];
    __shared__ float sv[SS];
    __shared__ float redA[16];
    __shared__ float redB[16];

    int row = b * SS + i;
    int   p = g_pred[row];
    float v = g_valid[row];
    sp[i] = p;
    sv[i] = v;
    __syncthreads();

    // total valid count
    float total = v;
    #pragma unroll
    for (int off = 16; off; off >>= 1) total += __shfl_down_sync(0xffffffffu, total, off);
    if ((i & 31) == 0) redA[i >> 5] = total;
    __syncthreads();
    if (i < 16) {
        float xx = redA[i];
        #pragma unroll
        for (int off = 8; off; off >>= 1) xx += __shfl_down_sync(0xffffu, xx, off);
        if (i == 0) redA[0] = xx;
    }
    __syncthreads();
    total = redA[0];
    __syncthreads();

    // per-position count + first-occurrence flag
    float c = 0.f;
    bool first = (v > 0.f);
    for (int j = 0; j < SS; j++) {
        bool match = (sp[j] == p) && (sv[j] > 0.f);
        c += match ? 1.f : 0.f;
        if (match && j < i) first = false;
    }

    float ent = 0.f, nu = 0.f;
    if (v > 0.f && first) {
        float pr = c / fmaxf(total, 1.f);
        ent = -pr * logf(pr + 1e-10f);
        nu  = 1.f;
    }

    // reduce ent and nu
    #pragma unroll
    for (int off = 16; off; off >>= 1) {
        ent += __shfl_down_sync(0xffffffffu, ent, off);
        nu  += __shfl_down_sync(0xffffffffu, nu,  off);
    }
    if ((i & 31) == 0) { redA[i >> 5] = ent; redB[i >> 5] = nu; }
    __syncthreads();
    if (i < 16) {
        float ea = redA[i];
        float na = redB[i];
        #pragma unroll
        for (int off = 8; off; off >>= 1) {
            ea += __shfl_down_sync(0xffffu, ea, off);
            na += __shfl_down_sync(0xffffu, na, off);
        }
        if (i == 0) {
            g_per_b[b] = (total > 0.f) ? (1.f - ea / logf(na + 1.f)) : 0.f;
        }
    }
}

// ---------------------------------------------------------------------------
// Kernel 3: final reduction -> out[0..2] = (total, ce, rep)
// ---------------------------------------------------------------------------
__global__ void __launch_bounds__(1024) final_kernel(float* __restrict__ out, int out_size) {
    const int tid = threadIdx.x;
    float spt = 0.f, svl = 0.f;
    for (int i = tid; i < ROWS; i += 1024) {
        spt += g_per_tok[i];
        svl += g_valid[i];
    }
    #pragma unroll
    for (int off = 16; off; off >>= 1) {
        spt += __shfl_down_sync(0xffffffffu, spt, off);
        svl += __shfl_down_sync(0xffffffffu, svl, off);
    }
    __shared__ float r1[32], r2[32];
    int wid = tid >> 5;
    if ((tid & 31) == 0) { r1[wid] = spt; r2[wid] = svl; }
    __syncthreads();
    if (tid < 32) {
        float a = r1[tid];
        float bq = r2[tid];
        #pragma unroll
        for (int off = 16; off; off >>= 1) {
            a  += __shfl_down_sync(0xffffffffu, a,  off);
            bq += __shfl_down_sync(0xffffffffu, bq, off);
        }
        if (tid == 0) {
            float ce = a / fmaxf(bq, 1.f);
            float rep = 0.f;
            #pragma unroll
            for (int b = 0; b < BB; b++) rep += g_per_b[b];
            rep /= (float)BB;
            float total = ce + REP_W * rep;
            out[0] = total;
            if (out_size > 1) out[1] = ce;
            if (out_size > 2) out[2] = rep;
        }
    }
}

extern "C" void kernel_launch(void* const* d_in, const int* in_sizes, int n_in,
                              void* d_out, int out_size) {
    const float* logits = (const float*)d_in[0];
    const void*  labels = d_in[1];
    // d_in[2] = input_ids (unused by the math; only gates rep != 0, and it is present)

    detect_label_width<<<1, 256>>>((const int*)labels, ROWS);
    row_kernel<<<ROWS, 256>>>(logits, labels);
    rep_kernel<<<BB, SS>>>();
    final_kernel<<<1, 1024>>>((float*)d_out, out_size);
}